// round 8
// baseline (speedup 1.0000x reference)
#include <cuda_runtime.h>
#include <math.h>

#define HWQ   65536
#define DIMQ  192
#define QKVC  576
#define BQ    4
#define HEADSQ 6

// ---------------- scratch (static device globals; no allocation) ------------
__device__ float g_qkv1[150994944];           // [4,576,65536] after 1x1 conv
__device__ float g_qkv2[150994944];           // [4,576,65536] after dw conv
__device__ float g_spn[3 * HWQ];              // normalized superpixel
__device__ float g_spmean[DIMQ * HWQ];        // proj conv output (batch-invariant)
__device__ float g_qinv[BQ * DIMQ * 256];     // 1/||q_row||_w
__device__ float g_part[24 * 16 * 1088];      // partial S (1024) + nq2(32) + nk2(32)
__device__ float g_A[BQ * HEADSQ * 32 * 32];  // combined attention matrices
__device__ float g_M[BQ * DIMQ * DIMQ];       // W_out @ blockdiag(A)

// ---------------- K0a: l2-normalize superpixel rows over W ------------------
__global__ void k_sp_norm(const float* __restrict__ sp) {
    int row = blockIdx.x * 8 + (threadIdx.x >> 5);   // 3*256 = 768 rows
    int lane = threadIdx.x & 31;
    if (row >= 768) return;
    const float* p = sp + row * 256;
    float s = 0.f;
    for (int i = lane; i < 256; i += 32) { float v = p[i]; s += v * v; }
    for (int o = 16; o > 0; o >>= 1) s += __shfl_xor_sync(0xffffffffu, s, o);
    float inv = 1.0f / fmaxf(sqrtf(s), 1e-12f);
    for (int i = lane; i < 256; i += 32) g_spn[row * 256 + i] = p[i] * inv;
}

// ---------------- K0b: 3x3 conv (3 -> 192 ch) on normalized sp -------------
__global__ void k_spconv(const float* __restrict__ proj_w) {
    int x = threadIdx.x;        // 256
    int y = blockIdx.x;         // 256
    int o = blockIdx.y;         // 192
    float acc = 0.f;
    #pragma unroll
    for (int i = 0; i < 3; i++) {
        #pragma unroll
        for (int dy = -1; dy <= 1; dy++) {
            int yy = y + dy; if (yy < 0 || yy >= 256) continue;
            #pragma unroll
            for (int dx = -1; dx <= 1; dx++) {
                int xx = x + dx; if (xx < 0 || xx >= 256) continue;
                acc += __ldg(&proj_w[((o * 3 + i) * 3 + (dy + 1)) * 3 + (dx + 1)])
                     * g_spn[(i * 256 + yy) * 256 + xx];
            }
        }
    }
    g_spmean[((size_t)o * 256 + y) * 256 + x] = acc;
}

// ---------------- double-buffered SIMT SGEMM: C[M,N] = A[M,K] @ B[K,N] ------
// BM=96, BN=128, BK=16, 256 threads, 6x8 micro-tile per thread.
// K is compile-time (192 here): full static trip count for the main loop.
template <int K>
__global__ __launch_bounds__(256) void k_gemm(
    const float* __restrict__ A, const float* __restrict__ Bm, float* __restrict__ Cm,
    int N, long long sA, long long sB, long long sC)
{
    A  += (size_t)blockIdx.z * sA;
    Bm += (size_t)blockIdx.z * sB;
    Cm += (size_t)blockIdx.z * sC;
    __shared__ float As[2][16][100];
    __shared__ float Bs[2][16][128];
    int tid = threadIdx.x;
    int m0 = blockIdx.y * 96;
    int n0 = blockIdx.x * 128;
    int tr = tid >> 4, tc = tid & 15;       // 16 x 16 thread grid
    int r0 = tr * 6, c0 = tc * 8;
    float acc[6][8];
    #pragma unroll
    for (int i = 0; i < 6; i++)
        #pragma unroll
        for (int j = 0; j < 8; j++) acc[i][j] = 0.f;

    int ka = tid & 15, ma = tid >> 4;       // A tile: 96x16, 6 elems/thread
    int n4 = tid & 31, kb = tid >> 5;       // B tile: 16x128, 2 float4/thread

    // preload first tile into buffer 0
    #pragma unroll
    for (int i = 0; i < 6; i++)
        As[0][ka][ma + i * 16] = A[(size_t)(m0 + ma + i * 16) * K + ka];
    #pragma unroll
    for (int p = 0; p < 2; p++) {
        float4 v = *(const float4*)&Bm[(size_t)(kb + p * 8) * N + n0 + n4 * 4];
        *(float4*)&Bs[0][kb + p * 8][n4 * 4] = v;
    }
    __syncthreads();

    int buf = 0;
    #pragma unroll 1
    for (int k0 = 0; k0 < K; k0 += 16) {
        int kn = k0 + 16;
        float a_pref[6];
        float4 b_pref[2];
        if (kn < K) {
            #pragma unroll
            for (int i = 0; i < 6; i++)
                a_pref[i] = A[(size_t)(m0 + ma + i * 16) * K + kn + ka];
            #pragma unroll
            for (int p = 0; p < 2; p++)
                b_pref[p] = *(const float4*)&Bm[(size_t)(kn + kb + p * 8) * N + n0 + n4 * 4];
        }
        #pragma unroll
        for (int k = 0; k < 16; k++) {
            float a[6];
            #pragma unroll
            for (int i = 0; i < 6; i++) a[i] = As[buf][k][r0 + i];
            float4 b4lo = *(const float4*)&Bs[buf][k][c0];
            float4 b4hi = *(const float4*)&Bs[buf][k][c0 + 4];
            #pragma unroll
            for (int i = 0; i < 6; i++) {
                acc[i][0] += a[i] * b4lo.x;
                acc[i][1] += a[i] * b4lo.y;
                acc[i][2] += a[i] * b4lo.z;
                acc[i][3] += a[i] * b4lo.w;
                acc[i][4] += a[i] * b4hi.x;
                acc[i][5] += a[i] * b4hi.y;
                acc[i][6] += a[i] * b4hi.z;
                acc[i][7] += a[i] * b4hi.w;
            }
        }
        if (kn < K) {
            #pragma unroll
            for (int i = 0; i < 6; i++)
                As[buf ^ 1][ka][ma + i * 16] = a_pref[i];
            #pragma unroll
            for (int p = 0; p < 2; p++)
                *(float4*)&Bs[buf ^ 1][kb + p * 8][n4 * 4] = b_pref[p];
            __syncthreads();
        }
        buf ^= 1;
    }
    #pragma unroll
    for (int i = 0; i < 6; i++) {
        float4 olo = make_float4(acc[i][0], acc[i][1], acc[i][2], acc[i][3]);
        float4 ohi = make_float4(acc[i][4], acc[i][5], acc[i][6], acc[i][7]);
        *(float4*)&Cm[(size_t)(m0 + r0 + i) * N + n0 + c0]     = olo;
        *(float4*)&Cm[(size_t)(m0 + r0 + i) * N + n0 + c0 + 4] = ohi;
    }
}

// ---------------- K2: depthwise 3x3 (576 groups) + fused q row-norm ---------
// One block computes one full W-row of one (b,channel,y); for q channels
// (c < DIM) it also block-reduces sum(out^2) and writes g_qinv directly.
__global__ void k_dw(const float* __restrict__ dw_w) {
    int x = threadIdx.x;           // 256
    int y = blockIdx.x;            // 256
    int bc = blockIdx.y;           // 4*576
    int c = bc % QKVC;
    int b = bc / QKVC;
    const float* in = g_qkv1 + (size_t)bc * HWQ;
    const float* wp = dw_w + c * 9;
    float w[9];
    #pragma unroll
    for (int i = 0; i < 9; i++) w[i] = __ldg(&wp[i]);
    float acc = 0.f;
    #pragma unroll
    for (int dy = -1; dy <= 1; dy++) {
        int yy = y + dy; if (yy < 0 || yy >= 256) continue;
        const float* row = in + yy * 256;
        #pragma unroll
        for (int dx = -1; dx <= 1; dx++) {
            int xx = x + dx; if (xx < 0 || xx >= 256) continue;
            acc += w[(dy + 1) * 3 + (dx + 1)] * row[xx];
        }
    }
    g_qkv2[(size_t)bc * HWQ + y * 256 + x] = acc;

    if (c < DIMQ) {   // q channel: fused row L2-norm over W
        __shared__ float red[8];
        float s = acc * acc;
        #pragma unroll
        for (int o = 16; o > 0; o >>= 1) s += __shfl_xor_sync(0xffffffffu, s, o);
        if ((x & 31) == 0) red[x >> 5] = s;
        __syncthreads();
        if (x == 0) {
            float t = 0.f;
            #pragma unroll
            for (int i = 0; i < 8; i++) t += red[i];
            g_qinv[(b * DIMQ + c) * 256 + y] = 1.0f / fmaxf(sqrtf(t), 1e-12f);
        }
    }
}

// ---------------- K4: attention statistics S, nq2, nk2 ---------------------
// grid: (16 chunks of 4096, 24 bh-units), 256 threads, 2x2 micro-tile.
__global__ __launch_bounds__(256) void k_attn_part() {
    int bh = blockIdx.y;
    int b = bh / HEADSQ, hd = bh % HEADSQ;
    int n0 = blockIdx.x * 4096;
    __shared__ float qs[32][129];
    __shared__ float ks[32][129];
    int tid = threadIdx.x;
    float a00 = 0, a01 = 0, a10 = 0, a11 = 0;
    float nq = 0.f, nk = 0.f;
    int c0 = (tid >> 4) << 1;
    int d0 = (tid & 15) << 1;
    size_t qbase = (size_t)b * QKVC * HWQ;
    for (int t = 0; t < 32; t++) {
        int nt = n0 + t * 128;
        int y = nt >> 8;
        __syncthreads();
        for (int idx = tid; idx < 4096; idx += 256) {
            int c = idx >> 7, j = idx & 127;
            int ch = hd * 32 + c;
            float qv = g_qkv2[qbase + (size_t)ch * HWQ + nt + j];
            qs[c][j] = qv * g_qinv[(b * DIMQ + ch) * 256 + y]
                          * g_spmean[(size_t)ch * HWQ + nt + j];
            ks[c][j] = g_qkv2[qbase + (size_t)(DIMQ + ch) * HWQ + nt + j];
        }
        __syncthreads();
        if (tid < 32) {
            #pragma unroll 8
            for (int j = 0; j < 128; j++) { float v = qs[tid][j]; nq += v * v; }
        } else if (tid < 64) {
            #pragma unroll 8
            for (int j = 0; j < 128; j++) { float v = ks[tid - 32][j]; nk += v * v; }
        }
        #pragma unroll 4
        for (int j = 0; j < 128; j++) {
            float qa = qs[c0][j], qb = qs[c0 + 1][j];
            float kc = ks[d0][j], kd = ks[d0 + 1][j];
            a00 += qa * kc; a01 += qa * kd; a10 += qb * kc; a11 += qb * kd;
        }
    }
    size_t base = (size_t)(bh * 16 + blockIdx.x) * 1088;
    g_part[base + c0 * 32 + d0]           = a00;
    g_part[base + c0 * 32 + d0 + 1]       = a01;
    g_part[base + (c0 + 1) * 32 + d0]     = a10;
    g_part[base + (c0 + 1) * 32 + d0 + 1] = a11;
    if (tid < 32)       g_part[base + 1024 + tid]        = nq;
    else if (tid < 64)  g_part[base + 1056 + (tid - 32)] = nk;
}

// ---------------- K5: reduce partials, attn, top-k soften, softmax, mix -----
__global__ void k_attn_post(const float* __restrict__ temperature,
                            const float* __restrict__ attn_scales,
                            const float* __restrict__ w_mix) {
    int bh = blockIdx.x;
    int hd = bh % HEADSQ;
    __shared__ float Ssum[1088];
    __shared__ float attn[32][33];
    __shared__ float inq[32], ink[32];
    int tid = threadIdx.x;
    for (int idx = tid; idx < 1088; idx += 256) {
        float s = 0.f;
        for (int ch = 0; ch < 16; ch++) s += g_part[(size_t)(bh * 16 + ch) * 1088 + idx];
        Ssum[idx] = s;
    }
    __syncthreads();
    if (tid < 32)                 inq[tid]      = 1.f / fmaxf(sqrtf(Ssum[1024 + tid]), 1e-12f);
    else if (tid < 64)            ink[tid - 32] = 1.f / fmaxf(sqrtf(Ssum[1056 + tid - 32]), 1e-12f);
    __syncthreads();
    float temp = temperature[hd];
    for (int idx = tid; idx < 1024; idx += 256) {
        int c = idx >> 5, d = idx & 31;
        attn[c][d] = Ssum[idx] * inq[c] * ink[d] * temp;
    }
    __syncthreads();
    float w0 = w_mix[0], w1 = w_mix[1];
    float mw = fmaxf(w0, w1);
    float e0 = expf(w0 - mw), e1 = expf(w1 - mw);
    float wm0 = e0 / (e0 + e1), wm1 = e1 / (e0 + e1);
    float sc[4] = {attn_scales[0], attn_scales[1], attn_scales[2], attn_scales[3]};
    float ssum = sc[0] + sc[1] + sc[2] + sc[3];
    int warp = tid >> 5, lane = tid & 31;
    for (int r = 0; r < 4; r++) {
        int c = warp * 4 + r;
        float a = attn[c][lane];
        // warp bitonic ascending sort of a copy
        float v = a;
        #pragma unroll
        for (int k = 2; k <= 32; k <<= 1) {
            #pragma unroll
            for (int j = k >> 1; j > 0; j >>= 1) {
                float o = __shfl_xor_sync(0xffffffffu, v, j);
                bool up = ((lane & k) == 0);
                bool lower = ((lane & j) == 0);
                float mn = fminf(v, o), mx = fmaxf(v, o);
                v = (up == lower) ? mn : mx;
            }
        }
        float thr[4];
        thr[0] = __shfl_sync(0xffffffffu, v, 16);  // kk = 16
        thr[1] = __shfl_sync(0xffffffffu, v, 11);  // kk = 21
        thr[2] = __shfl_sync(0xffffffffu, v, 8);   // kk = 24
        thr[3] = __shfl_sync(0xffffffffu, v, 7);   // kk = 25
        float acc = wm0 * ssum * fmaxf(a, 0.f);
        #pragma unroll
        for (int i = 0; i < 4; i++) {
            float sv = (a >= thr[i]) ? a : a * 1e-6f;
            float m = sv;
            for (int o = 16; o > 0; o >>= 1) m = fmaxf(m, __shfl_xor_sync(0xffffffffu, m, o));
            float e = expf(sv - m);
            float se = e;
            for (int o = 16; o > 0; o >>= 1) se += __shfl_xor_sync(0xffffffffu, se, o);
            acc += wm1 * sc[i] * (e / se);
        }
        g_A[(size_t)bh * 1024 + c * 32 + lane] = acc;
    }
}

// ---------------- K6: M[b] = out_w @ blockdiag(A_combined) ------------------
__global__ void k_buildM(const float* __restrict__ out_w) {
    int o = blockIdx.x;     // 192
    int b = blockIdx.y;     // 4
    int j = threadIdx.x;    // 192
    int hd = j >> 5, d = j & 31;
    float s = 0.f;
    #pragma unroll
    for (int c = 0; c < 32; c++)
        s += out_w[o * DIMQ + hd * 32 + c] * g_A[(size_t)(b * HEADSQ + hd) * 1024 + c * 32 + d];
    g_M[((size_t)b * DIMQ + o) * DIMQ + j] = s;
}

// ---------------- host launcher ---------------------------------------------
extern "C" void kernel_launch(void* const* d_in, const int* in_sizes, int n_in,
                              void* d_out, int out_size) {
    const float* x           = (const float*)d_in[0];
    const float* sp          = (const float*)d_in[1];
    const float* qkv_w       = (const float*)d_in[2];
    const float* dw_w        = (const float*)d_in[3];
    const float* proj_w      = (const float*)d_in[4];
    const float* out_w       = (const float*)d_in[5];
    const float* temperature = (const float*)d_in[6];
    const float* attn_scales = (const float*)d_in[7];
    const float* w_mix       = (const float*)d_in[8];
    float* out = (float*)d_out;

    float *qkv1, *qkv2, *Mptr;
    cudaGetSymbolAddress((void**)&qkv1, g_qkv1);
    cudaGetSymbolAddress((void**)&qkv2, g_qkv2);
    cudaGetSymbolAddress((void**)&Mptr, g_M);

    // superpixel path (batch-invariant)
    k_sp_norm<<<96, 256>>>(sp);
    k_spconv<<<dim3(256, 192), 256>>>(proj_w);

    // qkv = dw3x3(conv1x1(x)); dw fuses the q row-norm
    k_gemm<DIMQ><<<dim3(HWQ / 128, QKVC / 96, BQ), 256>>>(
        qkv_w, x, qkv1, HWQ,
        0LL, (long long)DIMQ * HWQ, (long long)QKVC * HWQ);
    k_dw<<<dim3(256, BQ * QKVC), 256>>>(dw_w);

    // attention statistics and combined matrices
    k_attn_part<<<dim3(16, BQ * HEADSQ), 256>>>();
    k_attn_post<<<BQ * HEADSQ, 256>>>(temperature, attn_scales, w_mix);
    k_buildM<<<dim3(DIMQ, BQ), DIMQ>>>(out_w);

    // fused (attn @ V) + final 1x1 conv:  out[b] = M[b] @ V[b]
    k_gemm<DIMQ><<<dim3(HWQ / 128, DIMQ / 96, BQ), 256>>>(
        Mptr, qkv2 + (size_t)2 * DIMQ * HWQ, out, HWQ,
        (long long)DIMQ * DIMQ, (long long)QKVC * HWQ, (long long)DIMQ * HWQ);
}

// round 9
// speedup vs baseline: 1.2419x; 1.2419x over previous
#include <cuda_runtime.h>
#include <math.h>
#include <stdint.h>

#define HWQ   65536
#define DIMQ  192
#define QKVC  576
#define BQ    4
#define HEADSQ 6

// ---------------- scratch (static device globals; no allocation) ------------
__device__ float g_qkv1[150994944];           // [4,576,65536] after 1x1 conv
__device__ float g_qkv2[150994944];           // [4,576,65536] after dw conv
__device__ float g_spn[3 * HWQ];              // normalized superpixel
__device__ float g_spmean[DIMQ * HWQ];        // proj conv output (batch-invariant)
__device__ float g_qinv[BQ * DIMQ * 256];     // 1/||q_row||_w
__device__ float g_part[24 * 16 * 1088];      // partial S (1024) + nq2(32) + nk2(32)
__device__ float g_A[BQ * HEADSQ * 32 * 32];  // combined attention matrices
__device__ float g_M[BQ * DIMQ * DIMQ];       // W_out @ blockdiag(A)

// ---------------- K0a: l2-normalize superpixel rows over W ------------------
__global__ void k_sp_norm(const float* __restrict__ sp) {
    int row = blockIdx.x * 8 + (threadIdx.x >> 5);   // 3*256 = 768 rows
    int lane = threadIdx.x & 31;
    if (row >= 768) return;
    const float* p = sp + row * 256;
    float s = 0.f;
    for (int i = lane; i < 256; i += 32) { float v = p[i]; s += v * v; }
    for (int o = 16; o > 0; o >>= 1) s += __shfl_xor_sync(0xffffffffu, s, o);
    float inv = 1.0f / fmaxf(sqrtf(s), 1e-12f);
    for (int i = lane; i < 256; i += 32) g_spn[row * 256 + i] = p[i] * inv;
}

// ---------------- K0b: 3x3 conv (3 -> 192 ch) on normalized sp -------------
__global__ void k_spconv(const float* __restrict__ proj_w) {
    int x = threadIdx.x;        // 256
    int y = blockIdx.x;         // 256
    int o = blockIdx.y;         // 192
    float acc = 0.f;
    #pragma unroll
    for (int i = 0; i < 3; i++) {
        #pragma unroll
        for (int dy = -1; dy <= 1; dy++) {
            int yy = y + dy; if (yy < 0 || yy >= 256) continue;
            #pragma unroll
            for (int dx = -1; dx <= 1; dx++) {
                int xx = x + dx; if (xx < 0 || xx >= 256) continue;
                acc += __ldg(&proj_w[((o * 3 + i) * 3 + (dy + 1)) * 3 + (dx + 1)])
                     * g_spn[(i * 256 + yy) * 256 + xx];
            }
        }
    }
    g_spmean[((size_t)o * 256 + y) * 256 + x] = acc;
}

// ---------------- double-buffered SIMT SGEMM (fp32): C = A @ B --------------
// BM=96, BN=128, BK=16, 256 threads, 6x8 micro-tile. K compile-time.
template <int K>
__global__ __launch_bounds__(256) void k_gemm(
    const float* __restrict__ A, const float* __restrict__ Bm, float* __restrict__ Cm,
    int N, long long sA, long long sB, long long sC)
{
    A  += (size_t)blockIdx.z * sA;
    Bm += (size_t)blockIdx.z * sB;
    Cm += (size_t)blockIdx.z * sC;
    __shared__ float As[2][16][100];
    __shared__ float Bs[2][16][128];
    int tid = threadIdx.x;
    int m0 = blockIdx.y * 96;
    int n0 = blockIdx.x * 128;
    int tr = tid >> 4, tc = tid & 15;
    int r0 = tr * 6, c0 = tc * 8;
    float acc[6][8];
    #pragma unroll
    for (int i = 0; i < 6; i++)
        #pragma unroll
        for (int j = 0; j < 8; j++) acc[i][j] = 0.f;

    int ka = tid & 15, ma = tid >> 4;
    int n4 = tid & 31, kb = tid >> 5;

    #pragma unroll
    for (int i = 0; i < 6; i++)
        As[0][ka][ma + i * 16] = A[(size_t)(m0 + ma + i * 16) * K + ka];
    #pragma unroll
    for (int p = 0; p < 2; p++) {
        float4 v = *(const float4*)&Bm[(size_t)(kb + p * 8) * N + n0 + n4 * 4];
        *(float4*)&Bs[0][kb + p * 8][n4 * 4] = v;
    }
    __syncthreads();

    int buf = 0;
    #pragma unroll 1
    for (int k0 = 0; k0 < K; k0 += 16) {
        int kn = k0 + 16;
        float a_pref[6];
        float4 b_pref[2];
        if (kn < K) {
            #pragma unroll
            for (int i = 0; i < 6; i++)
                a_pref[i] = A[(size_t)(m0 + ma + i * 16) * K + kn + ka];
            #pragma unroll
            for (int p = 0; p < 2; p++)
                b_pref[p] = *(const float4*)&Bm[(size_t)(kn + kb + p * 8) * N + n0 + n4 * 4];
        }
        #pragma unroll
        for (int k = 0; k < 16; k++) {
            float a[6];
            #pragma unroll
            for (int i = 0; i < 6; i++) a[i] = As[buf][k][r0 + i];
            float4 b4lo = *(const float4*)&Bs[buf][k][c0];
            float4 b4hi = *(const float4*)&Bs[buf][k][c0 + 4];
            #pragma unroll
            for (int i = 0; i < 6; i++) {
                acc[i][0] += a[i] * b4lo.x;
                acc[i][1] += a[i] * b4lo.y;
                acc[i][2] += a[i] * b4lo.z;
                acc[i][3] += a[i] * b4lo.w;
                acc[i][4] += a[i] * b4hi.x;
                acc[i][5] += a[i] * b4hi.y;
                acc[i][6] += a[i] * b4hi.z;
                acc[i][7] += a[i] * b4hi.w;
            }
        }
        if (kn < K) {
            #pragma unroll
            for (int i = 0; i < 6; i++)
                As[buf ^ 1][ka][ma + i * 16] = a_pref[i];
            #pragma unroll
            for (int p = 0; p < 2; p++)
                *(float4*)&Bs[buf ^ 1][kb + p * 8][n4 * 4] = b_pref[p];
            __syncthreads();
        }
        buf ^= 1;
    }
    #pragma unroll
    for (int i = 0; i < 6; i++) {
        float4 olo = make_float4(acc[i][0], acc[i][1], acc[i][2], acc[i][3]);
        float4 ohi = make_float4(acc[i][4], acc[i][5], acc[i][6], acc[i][7]);
        *(float4*)&Cm[(size_t)(m0 + r0 + i) * N + n0 + c0]     = olo;
        *(float4*)&Cm[(size_t)(m0 + r0 + i) * N + n0 + c0 + 4] = ohi;
    }
}

// ---------------- tf32 tensor-core GEMM: C[192,N] = A[192,192] @ B[192,N] ---
// Linear output path only (no top-k downstream). Block 64x256, 8 warps of
// 32x64; mma.sync.m16n8k8 tf32, fp32 accumulate. Double-buffered smem.
__device__ __forceinline__ uint32_t f2tf(float f) {
    uint32_t u; asm("cvt.rna.tf32.f32 %0, %1;" : "=r"(u) : "f"(f)); return u;
}

__global__ __launch_bounds__(256) void k_gemm_tf32(
    const float* __restrict__ A, const float* __restrict__ Bm, float* __restrict__ Cm,
    long long sA, long long sB, long long sC)
{
    const int N = HWQ, K = DIMQ;
    A  += (size_t)blockIdx.z * sA;
    Bm += (size_t)blockIdx.z * sB;
    Cm += (size_t)blockIdx.z * sC;
    __shared__ uint32_t As[2][16][72];    // [k][m], padded stride 72
    __shared__ uint32_t Bs[2][16][264];   // [k][n], padded stride 264
    int tid = threadIdx.x;
    int lane = tid & 31, wid = tid >> 5;
    int m0 = blockIdx.y * 64;
    int n0 = blockIdx.x * 256;
    int mw = (wid & 1) * 32;              // warp m-offset
    int nw = (wid >> 1) * 64;             // warp n-offset
    float4 acc[2][8];
    #pragma unroll
    for (int i = 0; i < 2; i++)
        #pragma unroll
        for (int j = 0; j < 8; j++) acc[i][j] = make_float4(0.f, 0.f, 0.f, 0.f);

    int a_row = tid >> 2, a_kc = (tid & 3) * 4;   // A: 64 rows x 16 k

    // preload k-tile 0
    {
        float4 av = *(const float4*)&A[(size_t)(m0 + a_row) * K + a_kc];
        As[0][a_kc + 0][a_row] = f2tf(av.x);
        As[0][a_kc + 1][a_row] = f2tf(av.y);
        As[0][a_kc + 2][a_row] = f2tf(av.z);
        As[0][a_kc + 3][a_row] = f2tf(av.w);
        #pragma unroll
        for (int p = 0; p < 4; p++) {
            int q = p * 256 + tid;
            int br = q >> 6, bc4 = (q & 63) * 4;
            float4 bv = *(const float4*)&Bm[(size_t)br * N + n0 + bc4];
            uint4 t = make_uint4(f2tf(bv.x), f2tf(bv.y), f2tf(bv.z), f2tf(bv.w));
            *(uint4*)&Bs[0][br][bc4] = t;
        }
    }
    __syncthreads();

    int r = lane >> 2, cc = lane & 3;
    int buf = 0;
    #pragma unroll 1
    for (int k0 = 0; k0 < K; k0 += 16) {
        int kn = k0 + 16;
        float4 apf;
        float4 bpf[4];
        if (kn < K) {
            apf = *(const float4*)&A[(size_t)(m0 + a_row) * K + kn + a_kc];
            #pragma unroll
            for (int p = 0; p < 4; p++) {
                int q = p * 256 + tid;
                int br = q >> 6, bc4 = (q & 63) * 4;
                bpf[p] = *(const float4*)&Bm[(size_t)(kn + br) * N + n0 + bc4];
            }
        }
        #pragma unroll
        for (int ks = 0; ks < 16; ks += 8) {
            uint32_t a[2][4];
            #pragma unroll
            for (int mt = 0; mt < 2; mt++) {
                a[mt][0] = As[buf][ks + cc][mw + mt * 16 + r];
                a[mt][1] = As[buf][ks + cc][mw + mt * 16 + r + 8];
                a[mt][2] = As[buf][ks + cc + 4][mw + mt * 16 + r];
                a[mt][3] = As[buf][ks + cc + 4][mw + mt * 16 + r + 8];
            }
            uint32_t bb[8][2];
            #pragma unroll
            for (int nt = 0; nt < 8; nt++) {
                bb[nt][0] = Bs[buf][ks + cc][nw + nt * 8 + r];
                bb[nt][1] = Bs[buf][ks + cc + 4][nw + nt * 8 + r];
            }
            #pragma unroll
            for (int mt = 0; mt < 2; mt++)
                #pragma unroll
                for (int nt = 0; nt < 8; nt++) {
                    asm("mma.sync.aligned.m16n8k8.row.col.f32.tf32.tf32.f32 "
                        "{%0,%1,%2,%3}, {%4,%5,%6,%7}, {%8,%9}, {%0,%1,%2,%3};"
                        : "+f"(acc[mt][nt].x), "+f"(acc[mt][nt].y),
                          "+f"(acc[mt][nt].z), "+f"(acc[mt][nt].w)
                        : "r"(a[mt][0]), "r"(a[mt][1]), "r"(a[mt][2]), "r"(a[mt][3]),
                          "r"(bb[nt][0]), "r"(bb[nt][1]));
                }
        }
        if (kn < K) {
            As[buf ^ 1][a_kc + 0][a_row] = f2tf(apf.x);
            As[buf ^ 1][a_kc + 1][a_row] = f2tf(apf.y);
            As[buf ^ 1][a_kc + 2][a_row] = f2tf(apf.z);
            As[buf ^ 1][a_kc + 3][a_row] = f2tf(apf.w);
            #pragma unroll
            for (int p = 0; p < 4; p++) {
                int q = p * 256 + tid;
                int br = q >> 6, bc4 = (q & 63) * 4;
                uint4 t = make_uint4(f2tf(bpf[p].x), f2tf(bpf[p].y),
                                     f2tf(bpf[p].z), f2tf(bpf[p].w));
                *(uint4*)&Bs[buf ^ 1][br][bc4] = t;
            }
            __syncthreads();
        }
        buf ^= 1;
    }
    // epilogue: c0,c1 -> (row, 2cc..2cc+1); c2,c3 -> (row+8, ...)
    #pragma unroll
    for (int mt = 0; mt < 2; mt++)
        #pragma unroll
        for (int nt = 0; nt < 8; nt++) {
            int row = m0 + mw + mt * 16 + r;
            int col = n0 + nw + nt * 8 + cc * 2;
            float2 lo = make_float2(acc[mt][nt].x, acc[mt][nt].y);
            float2 hi = make_float2(acc[mt][nt].z, acc[mt][nt].w);
            *(float2*)&Cm[(size_t)row * N + col]       = lo;
            *(float2*)&Cm[(size_t)(row + 8) * N + col] = hi;
        }
}

// ---------------- K2: depthwise 3x3 via smem tile + fused q row-norm --------
// Block = 8 y-rows x 256 x-cols of one (b,channel). Input tile 10x258 in smem.
__global__ __launch_bounds__(256) void k_dw(const float* __restrict__ dw_w) {
    int ty = blockIdx.x;           // 0..31 (y tile of 8)
    int bc = blockIdx.y;           // 4*576
    int c = bc % QKVC;
    int b = bc / QKVC;
    int y0 = ty * 8;
    const float* in = g_qkv1 + (size_t)bc * HWQ;
    __shared__ float s[10][264];
    __shared__ float red[8][8];
    int tid = threadIdx.x;

    for (int i = tid; i < 10 * 258; i += 256) {
        int rr = i / 258, ccx = i % 258;
        int yy = y0 - 1 + rr, xx = ccx - 1;
        float v = 0.f;
        if (yy >= 0 && yy < 256 && xx >= 0 && xx < 256) v = in[yy * 256 + xx];
        s[rr][ccx] = v;
    }
    float w[9];
    #pragma unroll
    for (int i = 0; i < 9; i++) w[i] = __ldg(&dw_w[c * 9 + i]);
    __syncthreads();

    int x = tid;
    float p0[10], p1[10], p2[10];
    #pragma unroll
    for (int rr = 0; rr < 10; rr++) {
        p0[rr] = s[rr][x];
        p1[rr] = s[rr][x + 1];
        p2[rr] = s[rr][x + 2];
    }
    float acc[8];
    #pragma unroll
    for (int i = 0; i < 8; i++) {
        acc[i] = w[0] * p0[i]     + w[1] * p1[i]     + w[2] * p2[i]
               + w[3] * p0[i + 1] + w[4] * p1[i + 1] + w[5] * p2[i + 1]
               + w[6] * p0[i + 2] + w[7] * p1[i + 2] + w[8] * p2[i + 2];
        g_qkv2[(size_t)bc * HWQ + (y0 + i) * 256 + x] = acc[i];
    }

    if (c < DIMQ) {   // q channel: fused L2 row-norms for the 8 rows
        int lane = tid & 31, warp = tid >> 5;
        #pragma unroll
        for (int i = 0; i < 8; i++) {
            float sq = acc[i] * acc[i];
            #pragma unroll
            for (int o = 16; o > 0; o >>= 1) sq += __shfl_xor_sync(0xffffffffu, sq, o);
            if (lane == 0) red[warp][i] = sq;
        }
        __syncthreads();
        if (tid < 8) {
            float t = 0.f;
            #pragma unroll
            for (int wv = 0; wv < 8; wv++) t += red[wv][tid];
            g_qinv[(b * DIMQ + c) * 256 + y0 + tid] = 1.0f / fmaxf(sqrtf(t), 1e-12f);
        }
    }
}

// ---------------- K4: attention statistics S, nq2, nk2 ---------------------
__global__ __launch_bounds__(256) void k_attn_part() {
    int bh = blockIdx.y;
    int b = bh / HEADSQ, hd = bh % HEADSQ;
    int n0 = blockIdx.x * 4096;
    __shared__ float qs[32][129];
    __shared__ float ks[32][129];
    int tid = threadIdx.x;
    float a00 = 0, a01 = 0, a10 = 0, a11 = 0;
    float nq = 0.f, nk = 0.f;
    int c0 = (tid >> 4) << 1;
    int d0 = (tid & 15) << 1;
    size_t qbase = (size_t)b * QKVC * HWQ;
    for (int t = 0; t < 32; t++) {
        int nt = n0 + t * 128;
        int y = nt >> 8;
        __syncthreads();
        for (int idx = tid; idx < 4096; idx += 256) {
            int c = idx >> 7, j = idx & 127;
            int ch = hd * 32 + c;
            float qv = g_qkv2[qbase + (size_t)ch * HWQ + nt + j];
            qs[c][j] = qv * g_qinv[(b * DIMQ + ch) * 256 + y]
                          * g_spmean[(size_t)ch * HWQ + nt + j];
            ks[c][j] = g_qkv2[qbase + (size_t)(DIMQ + ch) * HWQ + nt + j];
        }
        __syncthreads();
        if (tid < 32) {
            #pragma unroll 8
            for (int j = 0; j < 128; j++) { float v = qs[tid][j]; nq += v * v; }
        } else if (tid < 64) {
            #pragma unroll 8
            for (int j = 0; j < 128; j++) { float v = ks[tid - 32][j]; nk += v * v; }
        }
        #pragma unroll 4
        for (int j = 0; j < 128; j++) {
            float qa = qs[c0][j], qb = qs[c0 + 1][j];
            float kc = ks[d0][j], kd = ks[d0 + 1][j];
            a00 += qa * kc; a01 += qa * kd; a10 += qb * kc; a11 += qb * kd;
        }
    }
    size_t base = (size_t)(bh * 16 + blockIdx.x) * 1088;
    g_part[base + c0 * 32 + d0]           = a00;
    g_part[base + c0 * 32 + d0 + 1]       = a01;
    g_part[base + (c0 + 1) * 32 + d0]     = a10;
    g_part[base + (c0 + 1) * 32 + d0 + 1] = a11;
    if (tid < 32)       g_part[base + 1024 + tid]        = nq;
    else if (tid < 64)  g_part[base + 1056 + (tid - 32)] = nk;
}

// ---------------- K5: reduce partials, attn, top-k soften, softmax, mix -----
__global__ void k_attn_post(const float* __restrict__ temperature,
                            const float* __restrict__ attn_scales,
                            const float* __restrict__ w_mix) {
    int bh = blockIdx.x;
    int hd = bh % HEADSQ;
    __shared__ float Ssum[1088];
    __shared__ float attn[32][33];
    __shared__ float inq[32], ink[32];
    int tid = threadIdx.x;
    for (int idx = tid; idx < 1088; idx += 256) {
        float s = 0.f;
        for (int ch = 0; ch < 16; ch++) s += g_part[(size_t)(bh * 16 + ch) * 1088 + idx];
        Ssum[idx] = s;
    }
    __syncthreads();
    if (tid < 32)                 inq[tid]      = 1.f / fmaxf(sqrtf(Ssum[1024 + tid]), 1e-12f);
    else if (tid < 64)            ink[tid - 32] = 1.f / fmaxf(sqrtf(Ssum[1056 + tid - 32]), 1e-12f);
    __syncthreads();
    float temp = temperature[hd];
    for (int idx = tid; idx < 1024; idx += 256) {
        int c = idx >> 5, d = idx & 31;
        attn[c][d] = Ssum[idx] * inq[c] * ink[d] * temp;
    }
    __syncthreads();
    float w0 = w_mix[0], w1 = w_mix[1];
    float mw = fmaxf(w0, w1);
    float e0 = expf(w0 - mw), e1 = expf(w1 - mw);
    float wm0 = e0 / (e0 + e1), wm1 = e1 / (e0 + e1);
    float sc[4] = {attn_scales[0], attn_scales[1], attn_scales[2], attn_scales[3]};
    float ssum = sc[0] + sc[1] + sc[2] + sc[3];
    int warp = tid >> 5, lane = tid & 31;
    for (int rr = 0; rr < 4; rr++) {
        int c = warp * 4 + rr;
        float a = attn[c][lane];
        float v = a;
        #pragma unroll
        for (int k = 2; k <= 32; k <<= 1) {
            #pragma unroll
            for (int j = k >> 1; j > 0; j >>= 1) {
                float o = __shfl_xor_sync(0xffffffffu, v, j);
                bool up = ((lane & k) == 0);
                bool lower = ((lane & j) == 0);
                float mn = fminf(v, o), mx = fmaxf(v, o);
                v = (up == lower) ? mn : mx;
            }
        }
        float thr[4];
        thr[0] = __shfl_sync(0xffffffffu, v, 16);  // kk = 16
        thr[1] = __shfl_sync(0xffffffffu, v, 11);  // kk = 21
        thr[2] = __shfl_sync(0xffffffffu, v, 8);   // kk = 24
        thr[3] = __shfl_sync(0xffffffffu, v, 7);   // kk = 25
        float acc = wm0 * ssum * fmaxf(a, 0.f);
        #pragma unroll
        for (int i = 0; i < 4; i++) {
            float sv = (a >= thr[i]) ? a : a * 1e-6f;
            float m = sv;
            for (int o = 16; o > 0; o >>= 1) m = fmaxf(m, __shfl_xor_sync(0xffffffffu, m, o));
            float e = expf(sv - m);
            float se = e;
            for (int o = 16; o > 0; o >>= 1) se += __shfl_xor_sync(0xffffffffu, se, o);
            acc += wm1 * sc[i] * (e / se);
        }
        g_A[(size_t)bh * 1024 + c * 32 + lane] = acc;
    }
}

// ---------------- K6: M[b] = out_w @ blockdiag(A_combined) ------------------
__global__ void k_buildM(const float* __restrict__ out_w) {
    int o = blockIdx.x;     // 192
    int b = blockIdx.y;     // 4
    int j = threadIdx.x;    // 192
    int hd = j >> 5, d = j & 31;
    float s = 0.f;
    #pragma unroll
    for (int c = 0; c < 32; c++)
        s += out_w[o * DIMQ + hd * 32 + c] * g_A[(size_t)(b * HEADSQ + hd) * 1024 + c * 32 + d];
    g_M[((size_t)b * DIMQ + o) * DIMQ + j] = s;
}

// ---------------- host launcher ---------------------------------------------
extern "C" void kernel_launch(void* const* d_in, const int* in_sizes, int n_in,
                              void* d_out, int out_size) {
    const float* x           = (const float*)d_in[0];
    const float* sp          = (const float*)d_in[1];
    const float* qkv_w       = (const float*)d_in[2];
    const float* dw_w        = (const float*)d_in[3];
    const float* proj_w      = (const float*)d_in[4];
    const float* out_w       = (const float*)d_in[5];
    const float* temperature = (const float*)d_in[6];
    const float* attn_scales = (const float*)d_in[7];
    const float* w_mix       = (const float*)d_in[8];
    float* out = (float*)d_out;

    float *qkv1, *qkv2, *Mptr;
    cudaGetSymbolAddress((void**)&qkv1, g_qkv1);
    cudaGetSymbolAddress((void**)&qkv2, g_qkv2);
    cudaGetSymbolAddress((void**)&Mptr, g_M);

    // superpixel path (batch-invariant)
    k_sp_norm<<<96, 256>>>(sp);
    k_spconv<<<dim3(256, 192), 256>>>(proj_w);

    // qkv = dw3x3(conv1x1(x)); dw fuses the q row-norm
    k_gemm<DIMQ><<<dim3(HWQ / 128, QKVC / 96, BQ), 256>>>(
        qkv_w, x, qkv1, HWQ,
        0LL, (long long)DIMQ * HWQ, (long long)QKVC * HWQ);
    k_dw<<<dim3(32, BQ * QKVC), 256>>>(dw_w);

    // attention statistics and combined matrices
    k_attn_part<<<dim3(16, BQ * HEADSQ), 256>>>();
    k_attn_post<<<BQ * HEADSQ, 256>>>(temperature, attn_scales, w_mix);
    k_buildM<<<dim3(DIMQ, BQ), DIMQ>>>(out_w);

    // fused (attn @ V) + final 1x1 conv via tf32 tensor cores
    k_gemm_tf32<<<dim3(HWQ / 256, DIMQ / 64, BQ), 256>>>(
        Mptr, qkv2 + (size_t)2 * DIMQ * HWQ, out,
        (long long)DIMQ * DIMQ, (long long)QKVC * HWQ, (long long)DIMQ * HWQ);
}

// round 16
// speedup vs baseline: 1.4101x; 1.1355x over previous
#include <cuda_runtime.h>
#include <math.h>
#include <stdint.h>

#define HWQ   65536
#define DIMQ  192
#define QKVC  576
#define BQ    4
#define HEADSQ 6

// ---------------- scratch (static device globals; no allocation) ------------
__device__ float g_qkv1[150994944];           // [4,576,65536] after 1x1 conv
__device__ float g_qkv2[150994944];           // [4,576,65536] after dw conv
__device__ float g_spn[3 * HWQ];              // normalized superpixel
__device__ float g_spmean[DIMQ * HWQ];        // proj conv output (batch-invariant)
__device__ float g_qinv[BQ * DIMQ * 256];     // 1/||q_row||_w
__device__ float g_part[24 * 16 * 1088];      // partial S (1024) + nq2(32) + nk2(32)
__device__ float g_A[BQ * HEADSQ * 32 * 32];  // combined attention matrices
__device__ float g_M[BQ * DIMQ * DIMQ];       // W_out @ blockdiag(A)

__device__ __forceinline__ uint32_t f2tf(float f) {
    uint32_t u; asm("cvt.rna.tf32.f32 %0, %1;" : "=r"(u) : "f"(f)); return u;
}
__device__ __forceinline__ void tf_split(float f, uint32_t& h, uint32_t& l) {
    h = f2tf(f);
    l = f2tf(f - __uint_as_float(h));
}

// ---------------- K0a: l2-normalize superpixel rows over W ------------------
__global__ void k_sp_norm(const float* __restrict__ sp) {
    int row = blockIdx.x * 8 + (threadIdx.x >> 5);   // 3*256 = 768 rows
    int lane = threadIdx.x & 31;
    if (row >= 768) return;
    const float* p = sp + row * 256;
    float s = 0.f;
    for (int i = lane; i < 256; i += 32) { float v = p[i]; s += v * v; }
    for (int o = 16; o > 0; o >>= 1) s += __shfl_xor_sync(0xffffffffu, s, o);
    float inv = 1.0f / fmaxf(sqrtf(s), 1e-12f);
    for (int i = lane; i < 256; i += 32) g_spn[row * 256 + i] = p[i] * inv;
}

// ---------------- K0b: 3x3 conv (3 -> 192 ch) on normalized sp -------------
__global__ void k_spconv(const float* __restrict__ proj_w) {
    int x = threadIdx.x;        // 256
    int y = blockIdx.x;         // 256
    int o = blockIdx.y;         // 192
    float acc = 0.f;
    #pragma unroll
    for (int i = 0; i < 3; i++) {
        #pragma unroll
        for (int dy = -1; dy <= 1; dy++) {
            int yy = y + dy; if (yy < 0 || yy >= 256) continue;
            #pragma unroll
            for (int dx = -1; dx <= 1; dx++) {
                int xx = x + dx; if (xx < 0 || xx >= 256) continue;
                acc += __ldg(&proj_w[((o * 3 + i) * 3 + (dy + 1)) * 3 + (dx + 1)])
                     * g_spn[(i * 256 + yy) * 256 + xx];
            }
        }
    }
    g_spmean[((size_t)o * 256 + y) * 256 + x] = acc;
}

// ---------------- 3xTF32 tensor-core GEMM: C[M,N] = A[M,K] @ B[K,N] ---------
// fp32-grade accuracy (err ~2^-21): Ah*Bh + Al*Bh + Ah*Bl per fragment pair.
// Block tile 64x128, BK=8, 8 warps of 32x32, double-buffered hi/lo smem.
// B tile fill: 8 rows x 128 cols = 256 float4s, exactly one per thread.
template <int K>
__global__ __launch_bounds__(256) void k_gemm_3xtf32(
    const float* __restrict__ A, const float* __restrict__ Bm, float* __restrict__ Cm,
    int N, long long sA, long long sB, long long sC)
{
    A  += (size_t)blockIdx.z * sA;
    Bm += (size_t)blockIdx.z * sB;
    Cm += (size_t)blockIdx.z * sC;
    __shared__ uint32_t Ah[2][8][72], Al[2][8][72];      // [k][m]
    __shared__ uint32_t Bh[2][8][136], Bl[2][8][136];    // [k][n]
    int tid = threadIdx.x;
    int lane = tid & 31, wid = tid >> 5;
    int m0 = blockIdx.y * 64;
    int n0 = blockIdx.x * 128;
    int mw = (wid & 1) * 32;
    int nw = (wid >> 1) * 32;
    float4 acc[2][4];
    #pragma unroll
    for (int i = 0; i < 2; i++)
        #pragma unroll
        for (int j = 0; j < 4; j++) acc[i][j] = make_float4(0.f, 0.f, 0.f, 0.f);

    int a_row = tid >> 2, a_kc = (tid & 3) * 2;   // A: 64 rows x 8 k, float2/thread
    int b_row = tid >> 5, b_c4 = (tid & 31) * 4;  // B: 8 rows x 32 float4s/row

    // preload k-tile 0
    {
        float2 av = *(const float2*)&A[(size_t)(m0 + a_row) * K + a_kc];
        tf_split(av.x, Ah[0][a_kc + 0][a_row], Al[0][a_kc + 0][a_row]);
        tf_split(av.y, Ah[0][a_kc + 1][a_row], Al[0][a_kc + 1][a_row]);
        float4 bv = *(const float4*)&Bm[(size_t)b_row * N + n0 + b_c4];
        tf_split(bv.x, Bh[0][b_row][b_c4 + 0], Bl[0][b_row][b_c4 + 0]);
        tf_split(bv.y, Bh[0][b_row][b_c4 + 1], Bl[0][b_row][b_c4 + 1]);
        tf_split(bv.z, Bh[0][b_row][b_c4 + 2], Bl[0][b_row][b_c4 + 2]);
        tf_split(bv.w, Bh[0][b_row][b_c4 + 3], Bl[0][b_row][b_c4 + 3]);
    }
    __syncthreads();

    int r = lane >> 2, cc = lane & 3;
    int buf = 0;
    #pragma unroll 1
    for (int k0 = 0; k0 < K; k0 += 8) {
        int kn = k0 + 8;
        float2 apf;
        float4 bpf;
        if (kn < K) {
            apf = *(const float2*)&A[(size_t)(m0 + a_row) * K + kn + a_kc];
            bpf = *(const float4*)&Bm[(size_t)(kn + b_row) * N + n0 + b_c4];
        }
        uint32_t ah[2][4], al[2][4];
        #pragma unroll
        for (int mt = 0; mt < 2; mt++) {
            int mb = mw + mt * 16 + r;
            ah[mt][0] = Ah[buf][cc][mb];     al[mt][0] = Al[buf][cc][mb];
            ah[mt][1] = Ah[buf][cc][mb + 8]; al[mt][1] = Al[buf][cc][mb + 8];
            ah[mt][2] = Ah[buf][cc + 4][mb]; al[mt][2] = Al[buf][cc + 4][mb];
            ah[mt][3] = Ah[buf][cc + 4][mb + 8]; al[mt][3] = Al[buf][cc + 4][mb + 8];
        }
        uint32_t bh[4][2], bl[4][2];
        #pragma unroll
        for (int nt = 0; nt < 4; nt++) {
            int nb = nw + nt * 8 + r;
            bh[nt][0] = Bh[buf][cc][nb];     bl[nt][0] = Bl[buf][cc][nb];
            bh[nt][1] = Bh[buf][cc + 4][nb]; bl[nt][1] = Bl[buf][cc + 4][nb];
        }
        #pragma unroll
        for (int mt = 0; mt < 2; mt++)
            #pragma unroll
            for (int nt = 0; nt < 4; nt++) {
                #define MMA_TF(AF, BF)                                              \
                    asm("mma.sync.aligned.m16n8k8.row.col.f32.tf32.tf32.f32 "       \
                        "{%0,%1,%2,%3}, {%4,%5,%6,%7}, {%8,%9}, {%0,%1,%2,%3};"     \
                        : "+f"(acc[mt][nt].x), "+f"(acc[mt][nt].y),                 \
                          "+f"(acc[mt][nt].z), "+f"(acc[mt][nt].w)                  \
                        : "r"(AF[mt][0]), "r"(AF[mt][1]), "r"(AF[mt][2]),           \
                          "r"(AF[mt][3]), "r"(BF[nt][0]), "r"(BF[nt][1]))
                MMA_TF(ah, bh);
                MMA_TF(al, bh);
                MMA_TF(ah, bl);
                #undef MMA_TF
            }
        if (kn < K) {
            tf_split(apf.x, Ah[buf ^ 1][a_kc + 0][a_row], Al[buf ^ 1][a_kc + 0][a_row]);
            tf_split(apf.y, Ah[buf ^ 1][a_kc + 1][a_row], Al[buf ^ 1][a_kc + 1][a_row]);
            tf_split(bpf.x, Bh[buf ^ 1][b_row][b_c4 + 0], Bl[buf ^ 1][b_row][b_c4 + 0]);
            tf_split(bpf.y, Bh[buf ^ 1][b_row][b_c4 + 1], Bl[buf ^ 1][b_row][b_c4 + 1]);
            tf_split(bpf.z, Bh[buf ^ 1][b_row][b_c4 + 2], Bl[buf ^ 1][b_row][b_c4 + 2]);
            tf_split(bpf.w, Bh[buf ^ 1][b_row][b_c4 + 3], Bl[buf ^ 1][b_row][b_c4 + 3]);
            __syncthreads();
        }
        buf ^= 1;
    }
    #pragma unroll
    for (int mt = 0; mt < 2; mt++)
        #pragma unroll
        for (int nt = 0; nt < 4; nt++) {
            int row = m0 + mw + mt * 16 + r;
            int col = n0 + nw + nt * 8 + cc * 2;
            float2 lo = make_float2(acc[mt][nt].x, acc[mt][nt].y);
            float2 hi = make_float2(acc[mt][nt].z, acc[mt][nt].w);
            *(float2*)&Cm[(size_t)row * N + col]       = lo;
            *(float2*)&Cm[(size_t)(row + 8) * N + col] = hi;
        }
}

// ---------------- 1xTF32 tensor-core GEMM (validated): final M @ V ----------
__global__ __launch_bounds__(256) void k_gemm_tf32(
    const float* __restrict__ A, const float* __restrict__ Bm, float* __restrict__ Cm,
    long long sA, long long sB, long long sC)
{
    const int N = HWQ, K = DIMQ;
    A  += (size_t)blockIdx.z * sA;
    Bm += (size_t)blockIdx.z * sB;
    Cm += (size_t)blockIdx.z * sC;
    __shared__ uint32_t As[2][16][72];
    __shared__ uint32_t Bs[2][16][264];
    int tid = threadIdx.x;
    int lane = tid & 31, wid = tid >> 5;
    int m0 = blockIdx.y * 64;
    int n0 = blockIdx.x * 256;
    int mw = (wid & 1) * 32;
    int nw = (wid >> 1) * 64;
    float4 acc[2][8];
    #pragma unroll
    for (int i = 0; i < 2; i++)
        #pragma unroll
        for (int j = 0; j < 8; j++) acc[i][j] = make_float4(0.f, 0.f, 0.f, 0.f);

    int a_row = tid >> 2, a_kc = (tid & 3) * 4;
    {
        float4 av = *(const float4*)&A[(size_t)(m0 + a_row) * K + a_kc];
        As[0][a_kc + 0][a_row] = f2tf(av.x);
        As[0][a_kc + 1][a_row] = f2tf(av.y);
        As[0][a_kc + 2][a_row] = f2tf(av.z);
        As[0][a_kc + 3][a_row] = f2tf(av.w);
        #pragma unroll
        for (int p = 0; p < 4; p++) {
            int q = p * 256 + tid;
            int br = q >> 6, bc4 = (q & 63) * 4;
            float4 bv = *(const float4*)&Bm[(size_t)br * N + n0 + bc4];
            uint4 t = make_uint4(f2tf(bv.x), f2tf(bv.y), f2tf(bv.z), f2tf(bv.w));
            *(uint4*)&Bs[0][br][bc4] = t;
        }
    }
    __syncthreads();

    int r = lane >> 2, cc = lane & 3;
    int buf = 0;
    #pragma unroll 1
    for (int k0 = 0; k0 < K; k0 += 16) {
        int kn = k0 + 16;
        float4 apf;
        float4 bpf[4];
        if (kn < K) {
            apf = *(const float4*)&A[(size_t)(m0 + a_row) * K + kn + a_kc];
            #pragma unroll
            for (int p = 0; p < 4; p++) {
                int q = p * 256 + tid;
                int br = q >> 6, bc4 = (q & 63) * 4;
                bpf[p] = *(const float4*)&Bm[(size_t)(kn + br) * N + n0 + bc4];
            }
        }
        #pragma unroll
        for (int ks = 0; ks < 16; ks += 8) {
            uint32_t a[2][4];
            #pragma unroll
            for (int mt = 0; mt < 2; mt++) {
                a[mt][0] = As[buf][ks + cc][mw + mt * 16 + r];
                a[mt][1] = As[buf][ks + cc][mw + mt * 16 + r + 8];
                a[mt][2] = As[buf][ks + cc + 4][mw + mt * 16 + r];
                a[mt][3] = As[buf][ks + cc + 4][mw + mt * 16 + r + 8];
            }
            uint32_t bb[8][2];
            #pragma unroll
            for (int nt = 0; nt < 8; nt++) {
                bb[nt][0] = Bs[buf][ks + cc][nw + nt * 8 + r];
                bb[nt][1] = Bs[buf][ks + cc + 4][nw + nt * 8 + r];
            }
            #pragma unroll
            for (int mt = 0; mt < 2; mt++)
                #pragma unroll
                for (int nt = 0; nt < 8; nt++) {
                    asm("mma.sync.aligned.m16n8k8.row.col.f32.tf32.tf32.f32 "
                        "{%0,%1,%2,%3}, {%4,%5,%6,%7}, {%8,%9}, {%0,%1,%2,%3};"
                        : "+f"(acc[mt][nt].x), "+f"(acc[mt][nt].y),
                          "+f"(acc[mt][nt].z), "+f"(acc[mt][nt].w)
                        : "r"(a[mt][0]), "r"(a[mt][1]), "r"(a[mt][2]), "r"(a[mt][3]),
                          "r"(bb[nt][0]), "r"(bb[nt][1]));
                }
        }
        if (kn < K) {
            As[buf ^ 1][a_kc + 0][a_row] = f2tf(apf.x);
            As[buf ^ 1][a_kc + 1][a_row] = f2tf(apf.y);
            As[buf ^ 1][a_kc + 2][a_row] = f2tf(apf.z);
            As[buf ^ 1][a_kc + 3][a_row] = f2tf(apf.w);
            #pragma unroll
            for (int p = 0; p < 4; p++) {
                int q = p * 256 + tid;
                int br = q >> 6, bc4 = (q & 63) * 4;
                uint4 t = make_uint4(f2tf(bpf[p].x), f2tf(bpf[p].y),
                                     f2tf(bpf[p].z), f2tf(bpf[p].w));
                *(uint4*)&Bs[buf ^ 1][br][bc4] = t;
            }
            __syncthreads();
        }
        buf ^= 1;
    }
    #pragma unroll
    for (int mt = 0; mt < 2; mt++)
        #pragma unroll
        for (int nt = 0; nt < 8; nt++) {
            int row = m0 + mw + mt * 16 + r;
            int col = n0 + nw + nt * 8 + cc * 2;
            float2 lo = make_float2(acc[mt][nt].x, acc[mt][nt].y);
            float2 hi = make_float2(acc[mt][nt].z, acc[mt][nt].w);
            *(float2*)&Cm[(size_t)row * N + col]       = lo;
            *(float2*)&Cm[(size_t)(row + 8) * N + col] = hi;
        }
}

// ---------------- K2: depthwise 3x3 via smem tile + fused q row-norm --------
__global__ __launch_bounds__(256) void k_dw(const float* __restrict__ dw_w) {
    int ty = blockIdx.x;           // 0..31 (y tile of 8)
    int bc = blockIdx.y;           // 4*576
    int c = bc % QKVC;
    int b = bc / QKVC;
    int y0 = ty * 8;
    const float* in = g_qkv1 + (size_t)bc * HWQ;
    __shared__ float s[10][264];
    int tid = threadIdx.x;

    #pragma unroll
    for (int rr = 0; rr < 10; rr++) {
        int yy = y0 - 1 + rr;
        bool vy = (yy >= 0 && yy < 256);
        s[rr][tid] = (vy && tid >= 1) ? in[yy * 256 + tid - 1] : 0.f;
        if (tid < 2) {
            int x2 = 255 + tid;   // cols 256,257 <-> input x 255,256
            s[rr][256 + tid] = (vy && x2 < 256) ? in[yy * 256 + x2] : 0.f;
        }
    }
    float w[9];
    #pragma unroll
    for (int i = 0; i < 9; i++) w[i] = __ldg(&dw_w[c * 9 + i]);
    __syncthreads();

    int x = tid;
    float p0[10], p1[10], p2[10];
    #pragma unroll
    for (int rr = 0; rr < 10; rr++) {
        p0[rr] = s[rr][x];
        p1[rr] = s[rr][x + 1];
        p2[rr] = s[rr][x + 2];
    }
    float acc[8];
    #pragma unroll
    for (int i = 0; i < 8; i++) {
        acc[i] = w[0] * p0[i]     + w[1] * p1[i]     + w[2] * p2[i]
               + w[3] * p0[i + 1] + w[4] * p1[i + 1] + w[5] * p2[i + 1]
               + w[6] * p0[i + 2] + w[7] * p1[i + 2] + w[8] * p2[i + 2];
        g_qkv2[(size_t)bc * HWQ + (y0 + i) * 256 + x] = acc[i];
    }

    if (c < DIMQ) {   // q channel: fused L2 row-norms via smem transpose
        __syncthreads();            // everyone done reading s
        #pragma unroll
        for (int i = 0; i < 8; i++) s[i][tid] = acc[i] * acc[i];
        __syncthreads();
        int warp = tid >> 5, lane = tid & 31;
        if (warp < 8) {
            float t = 0.f;
            #pragma unroll
            for (int seg = 0; seg < 8; seg++) t += s[warp][lane + seg * 32];
            #pragma unroll
            for (int o = 16; o > 0; o >>= 1) t += __shfl_xor_sync(0xffffffffu, t, o);
            if (lane == 0)
                g_qinv[(b * DIMQ + c) * 256 + y0 + warp] = 1.0f / fmaxf(sqrtf(t), 1e-12f);
        }
    }
}

// ---------------- K4: attention statistics S, nq2, nk2 ---------------------
__global__ __launch_bounds__(256) void k_attn_part() {
    int bh = blockIdx.y;
    int b = bh / HEADSQ, hd = bh % HEADSQ;
    int n0 = blockIdx.x * 4096;
    __shared__ float qs[32][129];
    __shared__ float ks[32][129];
    int tid = threadIdx.x;
    float a00 = 0, a01 = 0, a10 = 0, a11 = 0;
    float nq = 0.f, nk = 0.f;
    int c0 = (tid >> 4) << 1;
    int d0 = (tid & 15) << 1;
    size_t qbase = (size_t)b * QKVC * HWQ;
    for (int t = 0; t < 32; t++) {
        int nt = n0 + t * 128;
        int y = nt >> 8;
        __syncthreads();
        for (int idx = tid; idx < 4096; idx += 256) {
            int c = idx >> 7, j = idx & 127;
            int ch = hd * 32 + c;
            float qv = g_qkv2[qbase + (size_t)ch * HWQ + nt + j];
            qs[c][j] = qv * g_qinv[(b * DIMQ + ch) * 256 + y]
                          * g_spmean[(size_t)ch * HWQ + nt + j];
            ks[c][j] = g_qkv2[qbase + (size_t)(DIMQ + ch) * HWQ + nt + j];
        }
        __syncthreads();
        if (tid < 32) {
            #pragma unroll 8
            for (int j = 0; j < 128; j++) { float v = qs[tid][j]; nq += v * v; }
        } else if (tid < 64) {
            #pragma unroll 8
            for (int j = 0; j < 128; j++) { float v = ks[tid - 32][j]; nk += v * v; }
        }
        #pragma unroll 4
        for (int j = 0; j < 128; j++) {
            float qa = qs[c0][j], qb = qs[c0 + 1][j];
            float kc = ks[d0][j], kd = ks[d0 + 1][j];
            a00 += qa * kc; a01 += qa * kd; a10 += qb * kc; a11 += qb * kd;
        }
    }
    size_t base = (size_t)(bh * 16 + blockIdx.x) * 1088;
    g_part[base + c0 * 32 + d0]           = a00;
    g_part[base + c0 * 32 + d0 + 1]       = a01;
    g_part[base + (c0 + 1) * 32 + d0]     = a10;
    g_part[base + (c0 + 1) * 32 + d0 + 1] = a11;
    if (tid < 32)       g_part[base + 1024 + tid]        = nq;
    else if (tid < 64)  g_part[base + 1056 + (tid - 32)] = nk;
}

// ---------------- K5: reduce partials, attn, top-k soften, softmax, mix -----
__global__ void k_attn_post(const float* __restrict__ temperature,
                            const float* __restrict__ attn_scales,
                            const float* __restrict__ w_mix) {
    int bh = blockIdx.x;
    int hd = bh % HEADSQ;
    __shared__ float Ssum[1088];
    __shared__ float attn[32][33];
    __shared__ float inq[32], ink[32];
    int tid = threadIdx.x;
    for (int idx = tid; idx < 1088; idx += 256) {
        float s = 0.f;
        for (int ch = 0; ch < 16; ch++) s += g_part[(size_t)(bh * 16 + ch) * 1088 + idx];
        Ssum[idx] = s;
    }
    __syncthreads();
    if (tid < 32)                 inq[tid]      = 1.f / fmaxf(sqrtf(Ssum[1024 + tid]), 1e-12f);
    else if (tid < 64)            ink[tid - 32] = 1.f / fmaxf(sqrtf(Ssum[1056 + tid - 32]), 1e-12f);
    __syncthreads();
    float temp = temperature[hd];
    for (int idx = tid; idx < 1024; idx += 256) {
        int c = idx >> 5, d = idx & 31;
        attn[c][d] = Ssum[idx] * inq[c] * ink[d] * temp;
    }
    __syncthreads();
    float w0 = w_mix[0], w1 = w_mix[1];
    float mw = fmaxf(w0, w1);
    float e0 = expf(w0 - mw), e1 = expf(w1 - mw);
    float wm0 = e0 / (e0 + e1), wm1 = e1 / (e0 + e1);
    float sc[4] = {attn_scales[0], attn_scales[1], attn_scales[2], attn_scales[3]};
    float ssum = sc[0] + sc[1] + sc[2] + sc[3];
    int warp = tid >> 5, lane = tid & 31;
    for (int rr = 0; rr < 4; rr++) {
        int c = warp * 4 + rr;
        float a = attn[c][lane];
        float v = a;
        #pragma unroll
        for (int k = 2; k <= 32; k <<= 1) {
            #pragma unroll
            for (int j = k >> 1; j > 0; j >>= 1) {
                float o = __shfl_xor_sync(0xffffffffu, v, j);
                bool up = ((lane & k) == 0);
                bool lower = ((lane & j) == 0);
                float mn = fminf(v, o), mx = fmaxf(v, o);
                v = (up == lower) ? mn : mx;
            }
        }
        float thr[4];
        thr[0] = __shfl_sync(0xffffffffu, v, 16);  // kk = 16
        thr[1] = __shfl_sync(0xffffffffu, v, 11);  // kk = 21
        thr[2] = __shfl_sync(0xffffffffu, v, 8);   // kk = 24
        thr[3] = __shfl_sync(0xffffffffu, v, 7);   // kk = 25
        float acc = wm0 * ssum * fmaxf(a, 0.f);
        #pragma unroll
        for (int i = 0; i < 4; i++) {
            float sv = (a >= thr[i]) ? a : a * 1e-6f;
            float m = sv;
            for (int o = 16; o > 0; o >>= 1) m = fmaxf(m, __shfl_xor_sync(0xffffffffu, m, o));
            float e = expf(sv - m);
            float se = e;
            for (int o = 16; o > 0; o >>= 1) se += __shfl_xor_sync(0xffffffffu, se, o);
            acc += wm1 * sc[i] * (e / se);
        }
        g_A[(size_t)bh * 1024 + c * 32 + lane] = acc;
    }
}

// ---------------- K6: M[b] = out_w @ blockdiag(A_combined) ------------------
__global__ void k_buildM(const float* __restrict__ out_w) {
    int o = blockIdx.x;     // 192
    int b = blockIdx.y;     // 4
    int j = threadIdx.x;    // 192
    int hd = j >> 5, d = j & 31;
    float s = 0.f;
    #pragma unroll
    for (int c = 0; c < 32; c++)
        s += out_w[o * DIMQ + hd * 32 + c] * g_A[(size_t)(b * HEADSQ + hd) * 1024 + c * 32 + d];
    g_M[((size_t)b * DIMQ + o) * DIMQ + j] = s;
}

// ---------------- host launcher ---------------------------------------------
extern "C" void kernel_launch(void* const* d_in, const int* in_sizes, int n_in,
                              void* d_out, int out_size) {
    const float* x           = (const float*)d_in[0];
    const float* sp          = (const float*)d_in[1];
    const float* qkv_w       = (const float*)d_in[2];
    const float* dw_w        = (const float*)d_in[3];
    const float* proj_w      = (const float*)d_in[4];
    const float* out_w       = (const float*)d_in[5];
    const float* temperature = (const float*)d_in[6];
    const float* attn_scales = (const float*)d_in[7];
    const float* w_mix       = (const float*)d_in[8];
    float* out = (float*)d_out;

    float *qkv1, *qkv2, *Mptr;
    cudaGetSymbolAddress((void**)&qkv1, g_qkv1);
    cudaGetSymbolAddress((void**)&qkv2, g_qkv2);
    cudaGetSymbolAddress((void**)&Mptr, g_M);

    // superpixel path (batch-invariant)
    k_sp_norm<<<96, 256>>>(sp);
    k_spconv<<<dim3(256, 192), 256>>>(proj_w);

    // qkv = dw3x3(conv1x1(x)); conv1x1 in 3xTF32 (fp32-grade accuracy)
    k_gemm_3xtf32<DIMQ><<<dim3(HWQ / 128, QKVC / 64, BQ), 256>>>(
        qkv_w, x, qkv1, HWQ,
        0LL, (long long)DIMQ * HWQ, (long long)QKVC * HWQ);
    k_dw<<<dim3(32, BQ * QKVC), 256>>>(dw_w);

    // attention statistics and combined matrices
    k_attn_part<<<dim3(16, BQ * HEADSQ), 256>>>();
    k_attn_post<<<BQ * HEADSQ, 256>>>(temperature, attn_scales, w_mix);
    k_buildM<<<dim3(DIMQ, BQ), DIMQ>>>(out_w);

    // fused (attn @ V) + final 1x1 conv via tf32 tensor cores
    k_gemm_tf32<<<dim3(HWQ / 256, DIMQ / 64, BQ), 256>>>(
        Mptr, qkv2 + (size_t)2 * DIMQ * HWQ, out,
        (long long)DIMQ * DIMQ, (long long)QKVC * HWQ, (long long)DIMQ * HWQ);
}